// round 1
// baseline (speedup 1.0000x reference)
#include <cuda_runtime.h>
#include <math.h>

// out = bilinear_sample(image, affine_grid(theta))  transposed to NCHW.
// The reference's linearization term is identically zero in the forward pass
// (slope * (grid - stop_gradient(grid)) == slope * 0), so only the center
// bilinear sample matters.

__global__ __launch_bounds__(256)
void lin_xform_kernel(const float* __restrict__ image,
                      const float* __restrict__ theta,
                      float* __restrict__ out,
                      int B, int C, int Hi, int Wi, int H, int W)
{
    int tid = blockIdx.x * blockDim.x + threadIdx.x;
    int wq = W >> 2;
    int total = B * H * wq;
    if (tid >= total) return;

    int w4  = (tid % wq) << 2;
    int tmp = tid / wq;
    int h   = tmp % H;
    int b   = tmp / H;

    const float* th = theta + b * 6;
    float t00 = __ldg(th + 0), t01 = __ldg(th + 1), t02 = __ldg(th + 2);
    float t10 = __ldg(th + 3), t11 = __ldg(th + 4), t12 = __ldg(th + 5);

    // align_corners=True base coords: X = -1 + w * 2/(W-1), Y = -1 + h * 2/(H-1)
    float sx = 2.0f / (float)(W - 1);
    float sy = 2.0f / (float)(H - 1);
    float Y  = fmaf((float)h, sy, -1.0f);
    float cyx = fmaf(t01, Y, t02);   // gx = t00*X + cyx
    float cyy = fmaf(t11, Y, t12);   // gy = t10*X + cyy

    float hxw = 0.5f * (float)(Wi - 1);
    float hyh = 0.5f * (float)(Hi - 1);

    int planeHW = Hi * Wi;
    const float* imgb = image + (size_t)b * C * planeHW;

    float res[3][4];

    #pragma unroll
    for (int j = 0; j < 4; j++) {
        float X  = fmaf((float)(w4 + j), sx, -1.0f);
        float gx = fmaf(t00, X, cyx);
        float gy = fmaf(t10, X, cyy);

        // align_corners: ix = (gx+1)*0.5*(Wi-1)
        float ix = (gx + 1.0f) * hxw;
        float iy = (gy + 1.0f) * hyh;

        float x0f = floorf(ix), y0f = floorf(iy);
        float wx = ix - x0f,    wy = iy - y0f;
        int x0 = (int)x0f, y0 = (int)y0f;
        int x1 = x0 + 1,   y1 = y0 + 1;

        bool vx0 = (x0 >= 0) && (x0 <= Wi - 1);
        bool vx1 = (x1 >= 0) && (x1 <= Wi - 1);
        bool vy0 = (y0 >= 0) && (y0 <= Hi - 1);
        bool vy1 = (y1 >= 0) && (y1 <= Hi - 1);

        float ox = 1.0f - wx, oy = 1.0f - wy;
        float w00 = (vx0 && vy0) ? ox * oy : 0.0f;
        float w01 = (vx1 && vy0) ? wx * oy : 0.0f;
        float w10 = (vx0 && vy1) ? ox * wy : 0.0f;
        float w11 = (vx1 && vy1) ? wx * wy : 0.0f;

        int x0c = min(max(x0, 0), Wi - 1);
        int x1c = min(max(x1, 0), Wi - 1);
        int y0c = min(max(y0, 0), Hi - 1);
        int y1c = min(max(y1, 0), Hi - 1);

        int o00 = y0c * Wi + x0c;
        int o01 = y0c * Wi + x1c;
        int o10 = y1c * Wi + x0c;
        int o11 = y1c * Wi + x1c;

        #pragma unroll
        for (int c = 0; c < 3; c++) {
            const float* p = imgb + c * planeHW;
            float v = w00 * __ldg(p + o00);
            v = fmaf(w01, __ldg(p + o01), v);
            v = fmaf(w10, __ldg(p + o10), v);
            v = fmaf(w11, __ldg(p + o11), v);
            res[c][j] = v;
        }
    }

    #pragma unroll
    for (int c = 0; c < 3; c++) {
        float4 v4 = make_float4(res[c][0], res[c][1], res[c][2], res[c][3]);
        *reinterpret_cast<float4*>(out + ((size_t)(b * C + c) * H + h) * W + w4) = v4;
    }
}

static int isqrt_round(long long v) {
    int r = (int)(sqrt((double)v) + 0.5);
    while ((long long)r * r > v) r--;
    while ((long long)(r + 1) * (r + 1) <= v) r++;
    return r;
}

extern "C" void kernel_launch(void* const* d_in, const int* in_sizes, int n_in,
                              void* d_out, int out_size) {
    const float* image = (const float*)d_in[0];
    const float* theta = (const float*)d_in[1];
    float* out = (float*)d_out;

    int B = in_sizes[1] / 6;           // pMtrx is (B, 2, 3)
    int C = 3;
    long long imgPlane = (long long)in_sizes[0] / ((long long)B * C); // Hi*Wi
    int Hi = isqrt_round(imgPlane);    // square image
    int Wi = Hi;
    long long outPlane = (long long)out_size / ((long long)B * C);   // H*W
    int H = isqrt_round(outPlane);     // square output (H == W in this problem)
    int W = H;

    int total = B * H * (W >> 2);
    int threads = 256;
    int blocks = (total + threads - 1) / threads;
    lin_xform_kernel<<<blocks, threads>>>(image, theta, out, B, C, Hi, Wi, H, W);
}

// round 2
// speedup vs baseline: 1.2002x; 1.2002x over previous
#include <cuda_runtime.h>
#include <math.h>

// out = bilinear_sample(image, affine_grid(theta)) transposed to NCHW.
// Linearization term of the reference is identically zero (slope * (grid - g0) == 0).
//
// Layout: one block per (b, h) output row. 256 threads, each thread handles
// pixels w = tid, tid+256, tid+512, tid+768 (lane-major => coalesced gathers).

__global__ __launch_bounds__(256)
void lin_xform_kernel(const float* __restrict__ image,
                      const float* __restrict__ theta,
                      float* __restrict__ out,
                      int B, int C, int Hi, int Wi, int H, int W)
{
    int row = blockIdx.x;          // 0 .. B*H-1
    int h = row % H;
    int b = row / H;
    int tid = threadIdx.x;

    const float* th = theta + b * 6;
    float t00 = __ldg(th + 0), t01 = __ldg(th + 1), t02 = __ldg(th + 2);
    float t10 = __ldg(th + 3), t11 = __ldg(th + 4), t12 = __ldg(th + 5);

    // align_corners=True: X = -1 + w*2/(W-1), Y = -1 + h*2/(H-1)
    float sx = 2.0f / (float)(W - 1);
    float sy = 2.0f / (float)(H - 1);
    float Y  = fmaf((float)h, sy, -1.0f);
    float cyx = fmaf(t01, Y, t02);   // gx = t00*X + cyx
    float cyy = fmaf(t11, Y, t12);   // gy = t10*X + cyy

    float hxw = 0.5f * (float)(Wi - 1);
    float hyh = 0.5f * (float)(Hi - 1);

    int planeHW = Hi * Wi;
    const float* imgb = image + (size_t)b * C * planeHW;
    float* outrow = out + ((size_t)(b * C) * H + h) * W;   // channel 0 row
    size_t planeOut = (size_t)H * W;

    int nk = W / (int)blockDim.x;    // pixels per thread (4 for W=1024)

    for (int k = 0; k < nk; k++) {
        int w = tid + k * (int)blockDim.x;

        float X  = fmaf((float)w, sx, -1.0f);
        float gx = fmaf(t00, X, cyx);
        float gy = fmaf(t10, X, cyy);

        float ix = (gx + 1.0f) * hxw;
        float iy = (gy + 1.0f) * hyh;

        float x0f = floorf(ix), y0f = floorf(iy);
        float wx = ix - x0f,    wy = iy - y0f;
        int x0 = (int)x0f, y0 = (int)y0f;
        int x1 = x0 + 1,   y1 = y0 + 1;

        bool vx0 = (x0 >= 0) && (x0 < Wi);
        bool vx1 = (x1 >= 0) && (x1 < Wi);
        bool vy0 = (y0 >= 0) && (y0 < Hi);
        bool vy1 = (y1 >= 0) && (y1 < Hi);

        float ox = 1.0f - wx, oy = 1.0f - wy;
        float w00 = (vx0 && vy0) ? ox * oy : 0.0f;
        float w01 = (vx1 && vy0) ? wx * oy : 0.0f;
        float w10 = (vx0 && vy1) ? ox * wy : 0.0f;
        float w11 = (vx1 && vy1) ? wx * wy : 0.0f;

        int x0c = min(max(x0, 0), Wi - 1);
        int x1c = min(max(x1, 0), Wi - 1);
        int y0c = min(max(y0, 0), Hi - 1);
        int y1c = min(max(y1, 0), Hi - 1);

        int o00 = y0c * Wi + x0c;
        int o01 = y0c * Wi + x1c;
        int o10 = y1c * Wi + x0c;
        int o11 = y1c * Wi + x1c;

        #pragma unroll
        for (int c = 0; c < 3; c++) {
            const float* p = imgb + c * planeHW;
            float v = w00 * __ldg(p + o00);
            v = fmaf(w01, __ldg(p + o01), v);
            v = fmaf(w10, __ldg(p + o10), v);
            v = fmaf(w11, __ldg(p + o11), v);
            outrow[c * planeOut + w] = v;
        }
    }
}

static int isqrt_round(long long v) {
    int r = (int)(sqrt((double)v) + 0.5);
    while ((long long)r * r > v) r--;
    while ((long long)(r + 1) * (r + 1) <= v) r++;
    return r;
}

extern "C" void kernel_launch(void* const* d_in, const int* in_sizes, int n_in,
                              void* d_out, int out_size) {
    const float* image = (const float*)d_in[0];
    const float* theta = (const float*)d_in[1];
    float* out = (float*)d_out;

    int B = in_sizes[1] / 6;           // pMtrx is (B, 2, 3)
    int C = 3;
    long long imgPlane = (long long)in_sizes[0] / ((long long)B * C); // Hi*Wi
    int Hi = isqrt_round(imgPlane);    // square image
    int Wi = Hi;
    long long outPlane = (long long)out_size / ((long long)B * C);   // H*W
    int H = isqrt_round(outPlane);     // square output
    int W = H;

    int blocks = B * H;                // one block per output row
    lin_xform_kernel<<<blocks, 256>>>(image, theta, out, B, C, Hi, Wi, H, W);
}

// round 3
// speedup vs baseline: 1.3007x; 1.0837x over previous
#include <cuda_runtime.h>
#include <math.h>

// out = bilinear_sample(image, affine_grid(theta)) transposed to NCHW.
// Linearization term of the reference is identically zero (slope * (grid - g0) == 0).

// ---------------- specialized kernel: B x 3 x 1024 x 1024 ----------------
constexpr int S = 1024;
constexpr int PLANE = S * S;          // 1<<20 elems = 4 MB bytes

__global__ __launch_bounds__(256)
void lin_xform_1024(const float* __restrict__ image,
                    const float* __restrict__ theta,
                    float* __restrict__ out)
{
    int row = blockIdx.x;             // 0 .. B*1024-1
    int h = row & (S - 1);
    int b = row >> 10;
    int tid = threadIdx.x;

    const float* th = theta + b * 6;
    float t00 = __ldg(th + 0), t01 = __ldg(th + 1), t02 = __ldg(th + 2);
    float t10 = __ldg(th + 3), t11 = __ldg(th + 4), t12 = __ldg(th + 5);

    const float sx = 2.0f / (float)(S - 1);
    float Y   = fmaf((float)h, sx, -1.0f);
    float cyx = fmaf(t01, Y, t02);
    float cyy = fmaf(t11, Y, t12);
    const float half = 0.5f * (float)(S - 1);

    // Base everything on the CHANNEL-1 plane so ch0/ch2 are +/-4MB immediates.
    const float* img1 = image + (size_t)(b * 3 + 1) * PLANE;
    float* out1 = out + (size_t)(b * 3 + 1) * PLANE + (size_t)h * S;

    #pragma unroll
    for (int k = 0; k < 4; k++) {
        int w = tid + (k << 8);

        float X  = fmaf((float)w, sx, -1.0f);
        float ix = (fmaf(t00, X, cyx) + 1.0f) * half;
        float iy = (fmaf(t10, X, cyy) + 1.0f) * half;

        float x0f = floorf(ix), y0f = floorf(iy);
        float wx = ix - x0f,    wy = iy - y0f;
        int x0 = (int)x0f, y0 = (int)y0f;
        float ox = 1.0f - wx, oy = 1.0f - wy;

        float r0, r1, r2;

        if (((unsigned)x0 < (unsigned)(S - 1)) & ((unsigned)y0 < (unsigned)(S - 1))) {
            // interior fast path: no clamps, no masks
            float w00 = ox * oy, w01 = wx * oy, w10 = ox * wy, w11 = wx * wy;
            const float* q = img1 + (y0 << 10) + x0;   // channel-1 tap base

            r0 = w00 * __ldg(q - PLANE);
            r0 = fmaf(w01, __ldg(q - PLANE + 1), r0);
            r0 = fmaf(w10, __ldg(q - PLANE + S), r0);
            r0 = fmaf(w11, __ldg(q - PLANE + S + 1), r0);

            r1 = w00 * __ldg(q);
            r1 = fmaf(w01, __ldg(q + 1), r1);
            r1 = fmaf(w10, __ldg(q + S), r1);
            r1 = fmaf(w11, __ldg(q + S + 1), r1);

            r2 = w00 * __ldg(q + PLANE);
            r2 = fmaf(w01, __ldg(q + PLANE + 1), r2);
            r2 = fmaf(w10, __ldg(q + PLANE + S), r2);
            r2 = fmaf(w11, __ldg(q + PLANE + S + 1), r2);
        } else {
            // boundary path: reference semantics (clamp + zero invalid weights)
            int x1 = x0 + 1, y1 = y0 + 1;
            bool vx0 = (x0 >= 0) & (x0 < S);
            bool vx1 = (x1 >= 0) & (x1 < S);
            bool vy0 = (y0 >= 0) & (y0 < S);
            bool vy1 = (y1 >= 0) & (y1 < S);
            float w00 = (vx0 & vy0) ? ox * oy : 0.0f;
            float w01 = (vx1 & vy0) ? wx * oy : 0.0f;
            float w10 = (vx0 & vy1) ? ox * wy : 0.0f;
            float w11 = (vx1 & vy1) ? wx * wy : 0.0f;
            int x0c = min(max(x0, 0), S - 1);
            int x1c = min(max(x1, 0), S - 1);
            int y0c = min(max(y0, 0), S - 1);
            int y1c = min(max(y1, 0), S - 1);
            int o00 = (y0c << 10) + x0c;
            int o01 = (y0c << 10) + x1c;
            int o10 = (y1c << 10) + x0c;
            int o11 = (y1c << 10) + x1c;
            const float* q = img1;
            r0 = w00 * __ldg(q - PLANE + o00);
            r0 = fmaf(w01, __ldg(q - PLANE + o01), r0);
            r0 = fmaf(w10, __ldg(q - PLANE + o10), r0);
            r0 = fmaf(w11, __ldg(q - PLANE + o11), r0);
            r1 = w00 * __ldg(q + o00);
            r1 = fmaf(w01, __ldg(q + o01), r1);
            r1 = fmaf(w10, __ldg(q + o10), r1);
            r1 = fmaf(w11, __ldg(q + o11), r1);
            r2 = w00 * __ldg(q + PLANE + o00);
            r2 = fmaf(w01, __ldg(q + PLANE + o01), r2);
            r2 = fmaf(w10, __ldg(q + PLANE + o10), r2);
            r2 = fmaf(w11, __ldg(q + PLANE + o11), r2);
        }

        out1[w - PLANE] = r0;
        out1[w]         = r1;
        out1[w + PLANE] = r2;
    }
}

// ---------------- generic fallback ----------------
__global__ __launch_bounds__(256)
void lin_xform_generic(const float* __restrict__ image,
                       const float* __restrict__ theta,
                       float* __restrict__ out,
                       int B, int C, int Hi, int Wi, int H, int W)
{
    int row = blockIdx.x;
    int h = row % H;
    int b = row / H;
    int tid = threadIdx.x;

    const float* th = theta + b * 6;
    float t00 = __ldg(th + 0), t01 = __ldg(th + 1), t02 = __ldg(th + 2);
    float t10 = __ldg(th + 3), t11 = __ldg(th + 4), t12 = __ldg(th + 5);

    float sx = 2.0f / (float)(W - 1);
    float sy = 2.0f / (float)(H - 1);
    float Y  = fmaf((float)h, sy, -1.0f);
    float cyx = fmaf(t01, Y, t02);
    float cyy = fmaf(t11, Y, t12);
    float hxw = 0.5f * (float)(Wi - 1);
    float hyh = 0.5f * (float)(Hi - 1);

    int planeHW = Hi * Wi;
    const float* imgb = image + (size_t)b * C * planeHW;
    float* outrow = out + ((size_t)(b * C) * H + h) * W;
    size_t planeOut = (size_t)H * W;

    for (int w = tid; w < W; w += blockDim.x) {
        float X  = fmaf((float)w, sx, -1.0f);
        float ix = (fmaf(t00, X, cyx) + 1.0f) * hxw;
        float iy = (fmaf(t10, X, cyy) + 1.0f) * hyh;
        float x0f = floorf(ix), y0f = floorf(iy);
        float wx = ix - x0f, wy = iy - y0f;
        int x0 = (int)x0f, y0 = (int)y0f;
        int x1 = x0 + 1, y1 = y0 + 1;
        bool vx0 = (x0 >= 0) & (x0 < Wi);
        bool vx1 = (x1 >= 0) & (x1 < Wi);
        bool vy0 = (y0 >= 0) & (y0 < Hi);
        bool vy1 = (y1 >= 0) & (y1 < Hi);
        float ox = 1.0f - wx, oy = 1.0f - wy;
        float w00 = (vx0 & vy0) ? ox * oy : 0.0f;
        float w01 = (vx1 & vy0) ? wx * oy : 0.0f;
        float w10 = (vx0 & vy1) ? ox * wy : 0.0f;
        float w11 = (vx1 & vy1) ? wx * wy : 0.0f;
        int x0c = min(max(x0, 0), Wi - 1);
        int x1c = min(max(x1, 0), Wi - 1);
        int y0c = min(max(y0, 0), Hi - 1);
        int y1c = min(max(y1, 0), Hi - 1);
        int o00 = y0c * Wi + x0c;
        int o01 = y0c * Wi + x1c;
        int o10 = y1c * Wi + x0c;
        int o11 = y1c * Wi + x1c;
        for (int c = 0; c < C; c++) {
            const float* p = imgb + c * planeHW;
            float v = w00 * __ldg(p + o00);
            v = fmaf(w01, __ldg(p + o01), v);
            v = fmaf(w10, __ldg(p + o10), v);
            v = fmaf(w11, __ldg(p + o11), v);
            outrow[c * planeOut + w] = v;
        }
    }
}

static int isqrt_round(long long v) {
    int r = (int)(sqrt((double)v) + 0.5);
    while ((long long)r * r > v) r--;
    while ((long long)(r + 1) * (r + 1) <= v) r++;
    return r;
}

extern "C" void kernel_launch(void* const* d_in, const int* in_sizes, int n_in,
                              void* d_out, int out_size) {
    const float* image = (const float*)d_in[0];
    const float* theta = (const float*)d_in[1];
    float* out = (float*)d_out;

    int B = in_sizes[1] / 6;           // pMtrx is (B, 2, 3)
    int C = 3;
    long long imgPlane = (long long)in_sizes[0] / ((long long)B * C);
    int Hi = isqrt_round(imgPlane);
    int Wi = Hi;
    long long outPlane = (long long)out_size / ((long long)B * C);
    int H = isqrt_round(outPlane);
    int W = H;

    if (C == 3 && Hi == S && Wi == S && H == S && W == S) {
        lin_xform_1024<<<B * S, 256>>>(image, theta, out);
    } else {
        lin_xform_generic<<<B * H, 256>>>(image, theta, out, B, C, Hi, Wi, H, W);
    }
}